// round 17
// baseline (speedup 1.0000x reference)
#include <cuda_runtime.h>

#define NQ      8
#define KCODES  1024
#define DIM     64
#define TOKENS  65536
#define TILE    128
#define CTA     256
#define WARPS   8
#define TPW     16
#define ROWF    68
#define TILEF   (TILE * ROWF)
#define NSTEP   (NQ * 16)          // 8 stages x 2 passes x 8 tiles

typedef unsigned long long u64;
typedef unsigned int u32;

__device__ float g_csq[NQ * KCODES];
__device__ u32   g_maxcsq[NQ];
__device__ float g_cbtf[NQ * KCODES * DIM];   // tf32, fragment-permuted rows

__device__ __forceinline__ u64 make_key(float s, u32 idx) {
    u32 b = __float_as_uint(s);
    u32 u = b ^ (u32)(((int)b >> 31) | 0x80000000);
    return ((u64)u << 32) | idx;
}
__device__ __forceinline__ u32 to_tf32(float f) {
    u32 r;
    asm("cvt.rna.tf32.f32 %0, %1;" : "=r"(r) : "f"(f));
    return r;
}
__device__ __forceinline__ u32 smem_u32(const void* p) {
    u32 a;
    asm("{ .reg .u64 t; cvta.to.shared.u64 t, %1; cvt.u32.u64 %0, t; }"
        : "=r"(a) : "l"(p));
    return a;
}
__device__ __forceinline__ void cp_async16(u32 dst, const void* src) {
    asm volatile("cp.async.cg.shared.global [%0], [%1], 16;"
                 :: "r"(dst), "l"(src) : "memory");
}
__device__ __forceinline__ void mma8(float& d0, float& d1, float& d2, float& d3,
                                     u32 a0, u32 a1, u32 a2, u32 a3,
                                     u32 b0, u32 b1) {
    asm("mma.sync.aligned.m16n8k8.row.col.f32.tf32.tf32.f32 "
        "{%0,%1,%2,%3},{%4,%5,%6,%7},{%8,%9},{%0,%1,%2,%3};"
        : "+f"(d0), "+f"(d1), "+f"(d2), "+f"(d3)
        : "r"(a0), "r"(a1), "r"(a2), "r"(a3), "r"(b0), "r"(b1));
}

// prep: exact csq, per-stage max, tf32 codebook in fragment order
__global__ void prep_kernel(const float* __restrict__ cb) {
    int r = blockIdx.x * blockDim.x + threadIdx.x;
    const float* row = cb + (size_t)r * DIM;
    float s = 0.f;
#pragma unroll
    for (int d = 0; d < DIM; d++)
        s = __fadd_rn(s, __fmul_rn(row[d], row[d]));
    g_csq[r] = s;
    atomicMax(&g_maxcsq[r >> 10], __float_as_uint(s));
#pragma unroll
    for (int d = 0; d < DIM; d++)
        g_cbtf[r * DIM + (d & 3) * 16 + (d >> 2)]
            = __uint_as_float(to_tf32(row[d]));
}

// exact rescore: sequential d-ascending fp32 fma chain (reference recipe)
__device__ __forceinline__ u64 rescore(const float* __restrict__ crow,
                                       const float* __restrict__ mrow,
                                       float rs, float cs, u32 code) {
    float dot = 0.f;
#pragma unroll 1
    for (int i = 0; i < DIM / 4; i++) {
        float4 cv = reinterpret_cast<const float4*>(crow)[i];
        float4 rv = reinterpret_cast<const float4*>(mrow)[i];
        dot = __fmaf_rn(rv.x, cv.x, dot);
        dot = __fmaf_rn(rv.y, cv.y, dot);
        dot = __fmaf_rn(rv.z, cv.z, dot);
        dot = __fmaf_rn(rv.w, cv.w, dot);
    }
    float s = __fadd_rn(__fsub_rn(rs, __fmul_rn(2.0f, dot)), cs);
    return make_key(s, code);
}

// one nb-block of 8 interleavable MMAs
#define MMA_BLOCK(D0, D1, D2, D3, F0, F1, F2, F3)                          \
    do {                                                                    \
        mma8(D0, D1, D2, D3, Ar[0][0], Ar[0][1], Ar[0][2], Ar[0][3],        \
             __float_as_uint(F0.x), __float_as_uint(F0.y));                 \
        mma8(D0, D1, D2, D3, Ar[1][0], Ar[1][1], Ar[1][2], Ar[1][3],        \
             __float_as_uint(F0.z), __float_as_uint(F0.w));                 \
        mma8(D0, D1, D2, D3, Ar[2][0], Ar[2][1], Ar[2][2], Ar[2][3],        \
             __float_as_uint(F1.x), __float_as_uint(F1.y));                 \
        mma8(D0, D1, D2, D3, Ar[3][0], Ar[3][1], Ar[3][2], Ar[3][3],        \
             __float_as_uint(F1.z), __float_as_uint(F1.w));                 \
        mma8(D0, D1, D2, D3, Ar[4][0], Ar[4][1], Ar[4][2], Ar[4][3],        \
             __float_as_uint(F2.x), __float_as_uint(F2.y));                 \
        mma8(D0, D1, D2, D3, Ar[5][0], Ar[5][1], Ar[5][2], Ar[5][3],        \
             __float_as_uint(F2.z), __float_as_uint(F2.w));                 \
        mma8(D0, D1, D2, D3, Ar[6][0], Ar[6][1], Ar[6][2], Ar[6][3],        \
             __float_as_uint(F3.x), __float_as_uint(F3.y));                 \
        mma8(D0, D1, D2, D3, Ar[7][0], Ar[7][1], Ar[7][2], Ar[7][3],        \
             __float_as_uint(F3.z), __float_as_uint(F3.w));                 \
    } while (0)

__global__ void __launch_bounds__(CTA)
rvq_kernel(const float* __restrict__ x,
           const float* __restrict__ cb,
           float* __restrict__ out) {
    extern __shared__ float sm[];
    float* tileB = sm;                       // [2][TILEF]
    float* scqB  = sm + 2 * TILEF;           // [2][TILE]
    float* myr_  = scqB + 2 * TILE;          // [WARPS][TPW][ROWF]

    const int tid  = threadIdx.x;
    const int wid  = tid >> 5;
    const int lane = tid & 31;
    const int g    = lane >> 2;
    const int t    = lane & 3;
    const int tokenBase = blockIdx.x * (WARPS * TPW) + wid * TPW;

    float* myr = myr_ + wid * TPW * ROWF;
    const u32 tile_b = smem_u32(tileB);

    float rs = 0.f;
    if (lane < TPW) {
        const float4* xr = reinterpret_cast<const float4*>(
            x + (size_t)(tokenBase + lane) * DIM);
        float* mrow = myr + lane * ROWF;
#pragma unroll
        for (int i = 0; i < DIM / 4; i++) {
            float4 v = xr[i];
            mrow[4 * i]     = v.x;  rs = __fadd_rn(rs, __fmul_rn(v.x, v.x));
            mrow[4 * i + 1] = v.y;  rs = __fadd_rn(rs, __fmul_rn(v.y, v.y));
            mrow[4 * i + 2] = v.z;  rs = __fadd_rn(rs, __fmul_rn(v.z, v.z));
            mrow[4 * i + 3] = v.w;  rs = __fadd_rn(rs, __fmul_rn(v.w, v.w));
        }
    }
    __syncwarp();
    float rs0 = __shfl_sync(0xffffffffu, rs, g);
    float rs1 = __shfl_sync(0xffffffffu, rs, g + 8);

    // prefetch step 0 tile + csq
    {
        const int row = tid >> 1, half = tid & 1;
        const float* src = g_cbtf + (size_t)row * DIM + half * 32;
        u32 dst = tile_b + (u32)((row * ROWF + half * 32) * 4);
#pragma unroll
        for (int i = 0; i < 8; i++)
            cp_async16(dst + 16u * i, src + 4 * i);
        asm volatile("cp.async.commit_group;" ::: "memory");
        if (tid < TILE) scqB[tid] = g_csq[tid];
    }

    u32 Ar[8][4];
    float bmax0 = 0.f, bmax1 = 0.f, min0 = 0.f, min1 = 0.f;
    float th0 = 0.f, th1 = 0.f;
    float tm0[8], tm1[8];                    // per-tile margin minima
    u64 key0 = 0, key1 = 0;
    const float C9 = 1.0f / 512.0f;

#pragma unroll 1
    for (int s = 0; s < NSTEP; s++) {
        const int q    = s >> 4;
        const int pass = (s >> 3) & 1;
        const int c    = s & 7;

        asm volatile("cp.async.wait_group 0;" ::: "memory");
        __syncthreads();

        if (s + 1 < NSTEP) {
            const int s2 = s + 1;
            const int q2 = s2 >> 4, c2 = s2 & 7;
            const int row = tid >> 1, half = tid & 1;
            const float* src = g_cbtf
                + ((size_t)q2 * KCODES + c2 * TILE + row) * DIM + half * 32;
            u32 dst = tile_b + (u32)(s2 & 1) * (TILEF * 4)
                    + (u32)((row * ROWF + half * 32) * 4);
#pragma unroll
            for (int i = 0; i < 8; i++)
                cp_async16(dst + 16u * i, src + 4 * i);
            asm volatile("cp.async.commit_group;" ::: "memory");
            if (tid < TILE)
                scqB[(s2 & 1) * TILE + tid]
                    = g_csq[q2 * KCODES + c2 * TILE + tid];
        }

        const float* tile = tileB + (s & 1) * TILEF;
        const float* scq  = scqB  + (s & 1) * TILE;

        if (pass == 0 && c == 0) {
#pragma unroll
            for (int kk = 0; kk < 8; kk++) {
                Ar[kk][0] = to_tf32(myr[g * ROWF + 8 * kk + t]);
                Ar[kk][1] = to_tf32(myr[(g + 8) * ROWF + 8 * kk + t]);
                Ar[kk][2] = to_tf32(myr[g * ROWF + 8 * kk + t + 4]);
                Ar[kk][3] = to_tf32(myr[(g + 8) * ROWF + 8 * kk + t + 4]);
            }
            const float maxcsq = __uint_as_float(g_maxcsq[q]);
            bmax0 = (rs0 + maxcsq) * C9;
            bmax1 = (rs1 + maxcsq) * C9;
            min0 = 3.4e38f;
            min1 = 3.4e38f;
#pragma unroll
            for (int i = 0; i < 8; i++) { tm0[i] = 3.4e38f; tm1[i] = 3.4e38f; }
        }
        if (pass == 1 && c == 0) {
            min0 = fminf(min0, __shfl_xor_sync(0xffffffffu, min0, 1));
            min0 = fminf(min0, __shfl_xor_sync(0xffffffffu, min0, 2));
            min1 = fminf(min1, __shfl_xor_sync(0xffffffffu, min1, 1));
            min1 = fminf(min1, __shfl_xor_sync(0xffffffffu, min1, 2));
            th0 = min0 + bmax0;
            th1 = min1 + bmax1;
            key0 = 0xFFFFFFFFFFFFFFFFull;
            key1 = 0xFFFFFFFFFFFFFFFFull;
        }

        // pass-2 tile skip: exact superset test; skips ONLY the compute loop
        bool skip = false;
        if (pass == 1) {
            bool fail = (tm0[c] > th0) && (tm1[c] > th1);
            skip = __all_sync(0xffffffffu, fail);
        }

        if (!skip) {
            const float* cbq = cb + (size_t)q * KCODES * DIM;

#pragma unroll 1
            for (int nb = 0; nb < TILE / 8; nb += 2) {
                float a0 = 0.f, a1 = 0.f, a2 = 0.f, a3 = 0.f;
                float b0 = 0.f, b1 = 0.f, b2 = 0.f, b3 = 0.f;
                const float4* browA = reinterpret_cast<const float4*>(
                    tile + (nb * 8 + g) * ROWF) + t * 4;
                const float4* browB = reinterpret_cast<const float4*>(
                    tile + ((nb + 1) * 8 + g) * ROWF) + t * 4;
                float4 fa0 = browA[0], fa1 = browA[1];
                float4 fa2 = browA[2], fa3 = browA[3];
                float4 fb0 = browB[0], fb1 = browB[1];
                float4 fb2 = browB[2], fb3 = browB[3];
                MMA_BLOCK(a0, a1, a2, a3, fa0, fa1, fa2, fa3);
                MMA_BLOCK(b0, b1, b2, b3, fb0, fb1, fb2, fb3);

#pragma unroll
                for (int h = 0; h < 2; h++) {
                    float d0 = h ? b0 : a0, d1 = h ? b1 : a1;
                    float d2 = h ? b2 : a2, d3 = h ? b3 : a3;
                    int   nbh = nb + h;
                    float cs0 = scq[nbh * 8 + 2 * t];
                    float cs1 = scq[nbh * 8 + 2 * t + 1];
                    float s00 = fmaf(-2.f, d0, rs0) + cs0;
                    float s01 = fmaf(-2.f, d1, rs0) + cs1;
                    float s10 = fmaf(-2.f, d2, rs1) + cs0;
                    float s11 = fmaf(-2.f, d3, rs1) + cs1;
                    float m00 = s00 - (rs0 + cs0) * C9;
                    float m01 = s01 - (rs0 + cs1) * C9;
                    float m10 = s10 - (rs1 + cs0) * C9;
                    float m11 = s11 - (rs1 + cs1) * C9;

                    if (pass == 0) {
                        min0 = fminf(min0, fminf(s00, s01));
                        min1 = fminf(min1, fminf(s10, s11));
                        tm0[c] = fminf(tm0[c], fminf(m00, m01));
                        tm1[c] = fminf(tm1[c], fminf(m10, m11));
                    } else {
                        u32 k0 = (u32)(c * TILE + nbh * 8 + 2 * t);
                        if (m00 <= th0) {
                            u64 k = rescore(cbq + (size_t)k0 * DIM,
                                            myr + g * ROWF, rs0, cs0, k0);
                            if (k < key0) key0 = k;
                        }
                        if (m01 <= th0) {
                            u64 k = rescore(cbq + (size_t)(k0 + 1) * DIM,
                                            myr + g * ROWF, rs0, cs1, k0 + 1);
                            if (k < key0) key0 = k;
                        }
                        if (m10 <= th1) {
                            u64 k = rescore(cbq + (size_t)k0 * DIM,
                                            myr + (g + 8) * ROWF, rs1, cs0, k0);
                            if (k < key1) key1 = k;
                        }
                        if (m11 <= th1) {
                            u64 k = rescore(cbq + (size_t)(k0 + 1) * DIM,
                                            myr + (g + 8) * ROWF, rs1, cs1,
                                            k0 + 1);
                            if (k < key1) key1 = k;
                        }
                    }
                }
            }
        }

        if (pass == 1 && c == 7) {
            // stage end: ALWAYS runs (merge keys, update residuals)
            u64 o;
            o = __shfl_xor_sync(0xffffffffu, key0, 1); if (o < key0) key0 = o;
            o = __shfl_xor_sync(0xffffffffu, key0, 2); if (o < key0) key0 = o;
            o = __shfl_xor_sync(0xffffffffu, key1, 1); if (o < key1) key1 = o;
            o = __shfl_xor_sync(0xffffffffu, key1, 2); if (o < key1) key1 = o;

            int srcl = (lane & 7) * 4;
            u64 kw0 = __shfl_sync(0xffffffffu, key0, srcl);
            u64 kw1 = __shfl_sync(0xffffffffu, key1, srcl);
            u64 kw  = (lane < 8) ? kw0 : kw1;

            rs = 0.f;
            if (lane < TPW) {
                float* mrow = myr + lane * ROWF;
                u32 bk = (u32)(kw & 0xFFFFull);
                const float4* crow = reinterpret_cast<const float4*>(
                    cb + ((size_t)q * KCODES + bk) * DIM);
#pragma unroll
                for (int i = 0; i < DIM / 4; i++) {
                    float4 v = crow[i];
                    float r0 = __fsub_rn(mrow[4 * i],     v.x);
                    float r1 = __fsub_rn(mrow[4 * i + 1], v.y);
                    float r2 = __fsub_rn(mrow[4 * i + 2], v.z);
                    float r3 = __fsub_rn(mrow[4 * i + 3], v.w);
                    mrow[4 * i]     = r0;
                    mrow[4 * i + 1] = r1;
                    mrow[4 * i + 2] = r2;
                    mrow[4 * i + 3] = r3;
                    rs = __fadd_rn(rs, __fmul_rn(r0, r0));
                    rs = __fadd_rn(rs, __fmul_rn(r1, r1));
                    rs = __fadd_rn(rs, __fmul_rn(r2, r2));
                    rs = __fadd_rn(rs, __fmul_rn(r3, r3));
                }
            }
            __syncwarp();
            rs0 = __shfl_sync(0xffffffffu, rs, g);
            rs1 = __shfl_sync(0xffffffffu, rs, g + 8);
        }
    }

    if (lane < TPW) {
        const float4* xr = reinterpret_cast<const float4*>(
            x + (size_t)(tokenBase + lane) * DIM);
        float4* orw = reinterpret_cast<float4*>(
            out + (size_t)(tokenBase + lane) * DIM);
        const float* mrow = myr + lane * ROWF;
#pragma unroll
        for (int i = 0; i < DIM / 4; i++) {
            float4 v = xr[i];
            v.x = __fsub_rn(v.x, mrow[4 * i]);
            v.y = __fsub_rn(v.y, mrow[4 * i + 1]);
            v.z = __fsub_rn(v.z, mrow[4 * i + 2]);
            v.w = __fsub_rn(v.w, mrow[4 * i + 3]);
            orw[i] = v;
        }
    }
}

extern "C" void kernel_launch(void* const* d_in, const int* in_sizes, int n_in,
                              void* d_out, int out_size) {
    const float* x;
    const float* cb;
    if (in_sizes[0] == NQ * KCODES * DIM) {
        cb = (const float*)d_in[0];
        x  = (const float*)d_in[1];
    } else {
        x  = (const float*)d_in[0];
        cb = (const float*)d_in[1];
    }
    float* out = (float*)d_out;

    const int smem_bytes = (2 * TILEF + 2 * TILE + WARPS * TPW * ROWF)
                           * (int)sizeof(float);
    cudaFuncSetAttribute(rvq_kernel,
                         cudaFuncAttributeMaxDynamicSharedMemorySize, smem_bytes);

    prep_kernel<<<(NQ * KCODES) / 128, 128>>>(cb);
    rvq_kernel<<<TOKENS / (WARPS * TPW), CTA, smem_bytes>>>(x, cb, out);
}